// round 10
// baseline (speedup 1.0000x reference)
#include <cuda_runtime.h>

// Comparator4Bit: A,B are (N,4) float32 with exact {0.0,1.0} entries.
// Column 0 = MSB (bit3) ... column 3 = LSB (bit0).
// Outputs: a_gt_b (N) | a_eq_b (N) concatenated in d_out.
//
// R10: champion R4 body (4 rows/thread, 8 front-batched warp-coalesced
// LDG.128 -> genuine MLP_eff=8 at regs~40; NO launch_bounds occupancy
// cap — R8/R9 proved forcing regs down serializes the load batch) with
// finer launch granularity: TPB=128, grid 8192 (12 CTAs/SM, same 48
// resident warps, smoother last-wave balance).

#define TPB 128
#define ROWS_PER_THREAD 4
#define ROWS_PER_BLOCK (TPB * ROWS_PER_THREAD)   // 512

__global__ void __launch_bounds__(TPB)
comparator4_kernel(const float4* __restrict__ A,
                   const float4* __restrict__ B,
                   float* __restrict__ out_gt,
                   float* __restrict__ out_eq,
                   int n)   // total rows
{
    int base = blockIdx.x * ROWS_PER_BLOCK + threadIdx.x;

    if (base + 3 * TPB < n) {
        // Fast path: front-batch all 8 coalesced LDG.128s.
        float4 a0 = __ldcs(A + base + 0 * TPB);
        float4 a1 = __ldcs(A + base + 1 * TPB);
        float4 a2 = __ldcs(A + base + 2 * TPB);
        float4 a3 = __ldcs(A + base + 3 * TPB);
        float4 b0 = __ldcs(B + base + 0 * TPB);
        float4 b1 = __ldcs(B + base + 1 * TPB);
        float4 b2 = __ldcs(B + base + 2 * TPB);
        float4 b3 = __ldcs(B + base + 3 * TPB);

        float4 av[ROWS_PER_THREAD] = {a0, a1, a2, a3};
        float4 bv[ROWS_PER_THREAD] = {b0, b1, b2, b3};
        float gt[ROWS_PER_THREAD], eq[ROWS_PER_THREAD];

#pragma unroll
        for (int k = 0; k < ROWS_PER_THREAD; k++) {
            float4 a = av[k];
            float4 b = bv[k];
            // x=bit3 (MSB), y=bit2, z=bit1, w=bit0
            bool e3 = (a.x == b.x), e2 = (a.y == b.y);
            bool e1 = (a.z == b.z), e0 = (a.w == b.w);
            bool g3 = (a.x > b.x), g2 = (a.y > b.y);
            bool g1 = (a.z > b.z), g0 = (a.w > b.w);
            bool agtb = g3 | (e3 & (g2 | (e2 & (g1 | (e1 & g0)))));
            bool aeqb = e3 & e2 & e1 & e0;
            gt[k] = agtb ? 1.0f : 0.0f;
            eq[k] = aeqb ? 1.0f : 0.0f;
        }

#pragma unroll
        for (int k = 0; k < ROWS_PER_THREAD; k++)
            __stcs(out_gt + base + k * TPB, gt[k]);
#pragma unroll
        for (int k = 0; k < ROWS_PER_THREAD; k++)
            __stcs(out_eq + base + k * TPB, eq[k]);
    } else {
        // Tail (unused for N = 4194304, kept for generality).
        for (int k = 0; k < ROWS_PER_THREAD; k++) {
            int i = base + k * TPB;
            if (i < n) {
                float4 a = __ldcs(A + i);
                float4 b = __ldcs(B + i);
                bool e3 = (a.x == b.x), e2 = (a.y == b.y);
                bool e1 = (a.z == b.z), e0 = (a.w == b.w);
                bool g3 = (a.x > b.x), g2 = (a.y > b.y);
                bool g1 = (a.z > b.z), g0 = (a.w > b.w);
                bool agtb = g3 | (e3 & (g2 | (e2 & (g1 | (e1 & g0)))));
                bool aeqb = e3 & e2 & e1 & e0;
                out_gt[i] = agtb ? 1.0f : 0.0f;
                out_eq[i] = aeqb ? 1.0f : 0.0f;
            }
        }
    }
}

extern "C" void kernel_launch(void* const* d_in, const int* in_sizes, int n_in,
                              void* d_out, int out_size)
{
    const float4* A = (const float4*)d_in[0];
    const float4* B = (const float4*)d_in[1];

    int n = in_sizes[0] / 4;          // rows (N)
    float* out = (float*)d_out;
    float* out_gt = out;                    // first N floats
    float* out_eq = out + (out_size / 2);   // second N floats

    int blocks = (n + ROWS_PER_BLOCK - 1) / ROWS_PER_BLOCK;
    comparator4_kernel<<<blocks, TPB>>>(A, B, out_gt, out_eq, n);
}

// round 11
// speedup vs baseline: 1.1544x; 1.1544x over previous
#include <cuda_runtime.h>

// Comparator4Bit: A,B are (N,4) float32 with exact {0.0,1.0} entries.
// Column 0 = MSB (bit3) ... column 3 = LSB (bit0).
// Outputs: a_gt_b (N) | a_eq_b (N) concatenated in d_out.
//
// R11 = session champion (R4/R6 config, best harness 24.48us, kernel
// 23.8us, DRAM 77.1%): TPB=256, 4 rows/thread, 8 front-batched
// warp-coalesced LDG.128 (thread t handles rows base + t + k*256 ->
// genuine MLP_eff=8 at regs=40), streaming cache hints, coalesced
// STG.32 outputs. Session sweep showed this is the roofline point:
//  - MLP sweep:   2 -> 76.1%,  8 -> 77.1-77.8%,  "16"/reg-capped -> 64-71%
//    (ptxas grants true MLP 8 only at ~40 regs; forcing regs down
//     serializes the load batch, raising occupancy but starving DRAM)
//  - persistence (grid-stride) serializes memory phases: 69%
// Do not re-apply launch_bounds caps or widen the batch.

#define TPB 256
#define ROWS_PER_THREAD 4
#define ROWS_PER_BLOCK (TPB * ROWS_PER_THREAD)   // 1024

__global__ void __launch_bounds__(TPB)
comparator4_kernel(const float4* __restrict__ A,
                   const float4* __restrict__ B,
                   float* __restrict__ out_gt,
                   float* __restrict__ out_eq,
                   int n)   // total rows
{
    int base = blockIdx.x * ROWS_PER_BLOCK + threadIdx.x;

    if (base + 3 * TPB < n) {
        // Fast path: front-batch all 8 coalesced LDG.128s.
        float4 a0 = __ldcs(A + base + 0 * TPB);
        float4 a1 = __ldcs(A + base + 1 * TPB);
        float4 a2 = __ldcs(A + base + 2 * TPB);
        float4 a3 = __ldcs(A + base + 3 * TPB);
        float4 b0 = __ldcs(B + base + 0 * TPB);
        float4 b1 = __ldcs(B + base + 1 * TPB);
        float4 b2 = __ldcs(B + base + 2 * TPB);
        float4 b3 = __ldcs(B + base + 3 * TPB);

        float4 av[ROWS_PER_THREAD] = {a0, a1, a2, a3};
        float4 bv[ROWS_PER_THREAD] = {b0, b1, b2, b3};
        float gt[ROWS_PER_THREAD], eq[ROWS_PER_THREAD];

#pragma unroll
        for (int k = 0; k < ROWS_PER_THREAD; k++) {
            float4 a = av[k];
            float4 b = bv[k];
            // x=bit3 (MSB), y=bit2, z=bit1, w=bit0
            bool e3 = (a.x == b.x), e2 = (a.y == b.y);
            bool e1 = (a.z == b.z), e0 = (a.w == b.w);
            bool g3 = (a.x > b.x), g2 = (a.y > b.y);
            bool g1 = (a.z > b.z), g0 = (a.w > b.w);
            bool agtb = g3 | (e3 & (g2 | (e2 & (g1 | (e1 & g0)))));
            bool aeqb = e3 & e2 & e1 & e0;
            gt[k] = agtb ? 1.0f : 0.0f;
            eq[k] = aeqb ? 1.0f : 0.0f;
        }

#pragma unroll
        for (int k = 0; k < ROWS_PER_THREAD; k++)
            __stcs(out_gt + base + k * TPB, gt[k]);
#pragma unroll
        for (int k = 0; k < ROWS_PER_THREAD; k++)
            __stcs(out_eq + base + k * TPB, eq[k]);
    } else {
        // Tail (unused for N = 4194304, kept for generality).
        for (int k = 0; k < ROWS_PER_THREAD; k++) {
            int i = base + k * TPB;
            if (i < n) {
                float4 a = __ldcs(A + i);
                float4 b = __ldcs(B + i);
                bool e3 = (a.x == b.x), e2 = (a.y == b.y);
                bool e1 = (a.z == b.z), e0 = (a.w == b.w);
                bool g3 = (a.x > b.x), g2 = (a.y > b.y);
                bool g1 = (a.z > b.z), g0 = (a.w > b.w);
                bool agtb = g3 | (e3 & (g2 | (e2 & (g1 | (e1 & g0)))));
                bool aeqb = e3 & e2 & e1 & e0;
                out_gt[i] = agtb ? 1.0f : 0.0f;
                out_eq[i] = aeqb ? 1.0f : 0.0f;
            }
        }
    }
}

extern "C" void kernel_launch(void* const* d_in, const int* in_sizes, int n_in,
                              void* d_out, int out_size)
{
    const float4* A = (const float4*)d_in[0];
    const float4* B = (const float4*)d_in[1];

    int n = in_sizes[0] / 4;          // rows (N)
    float* out = (float*)d_out;
    float* out_gt = out;                    // first N floats
    float* out_eq = out + (out_size / 2);   // second N floats

    int blocks = (n + ROWS_PER_BLOCK - 1) / ROWS_PER_BLOCK;
    comparator4_kernel<<<blocks, TPB>>>(A, B, out_gt, out_eq, n);
}